// round 9
// baseline (speedup 1.0000x reference)
#include <cuda_runtime.h>
#include <cstdint>
#include <cstddef>

// BioConvolution: 256 independent GEMMs  C_l[64,128] = A_l[64,1024] * B_l[1024,128]
//   A_l[m][k] = X[m, r*4+i, c*4+j, ch]  (k = i*256+j*64+ch, l = r*16+c)
//   B_l[k][f] = filters[l*131072 + k*128 + f]
//   out[(m*256+l)*128+f] = relu(C + bias[f])
//
// Round 9: warp-specialized producer/consumer. The fused loop capped L1 duty
// at ~76% (barrier-quiet windows). Producers (warps 4-7) free-run a 4-stage
// f16 ring (LDG f32 -> cvt -> STS) gated by per-stage empty mbarriers;
// consumers (warps 0-3, tile 32x64) gated by full mbarriers. Same verified
// fp16 mma/ldmatrix math -> rel_err identical.

namespace {

constexpr int NCH  = 16;                 // K chunks of 64
constexpr int AH   = 72;                 // A stride (halves) = 144B
constexpr int BH   = 136;                // B stride (halves) = 272B
constexpr int TA_B = 64 * AH * 2;        // 9216 B
constexpr int STG_B = TA_B + 64 * BH * 2;  // 26624 B per stage
constexpr int OFF_STG = 128;             // barriers live below
constexpr int SMEM_BYTES = OFF_STG + 4 * STG_B;  // 106624 -> 2 CTAs/SM

__device__ __forceinline__ uint32_t smem_u32(const void* p) {
    return static_cast<uint32_t>(__cvta_generic_to_shared(p));
}
__device__ __forceinline__ uint32_t pack_h2(float lo, float hi) {
    uint32_t d;
    asm("cvt.rn.f16x2.f32 %0, %1, %2;" : "=r"(d) : "f"(hi), "f"(lo));
    return d;
}
__device__ __forceinline__ void sts64(uint32_t a, uint32_t x, uint32_t y) {
    asm volatile("st.shared.v2.b32 [%0], {%1,%2};" :: "r"(a), "r"(x), "r"(y));
}
__device__ __forceinline__ void ldmx4(uint32_t* r, uint32_t a) {
    asm volatile("ldmatrix.sync.aligned.m8n8.x4.shared.b16 {%0,%1,%2,%3}, [%4];"
                 : "=r"(r[0]), "=r"(r[1]), "=r"(r[2]), "=r"(r[3]) : "r"(a));
}
__device__ __forceinline__ void ldmx4t(uint32_t* r, uint32_t a) {
    asm volatile("ldmatrix.sync.aligned.m8n8.x4.trans.shared.b16 {%0,%1,%2,%3}, [%4];"
                 : "=r"(r[0]), "=r"(r[1]), "=r"(r[2]), "=r"(r[3]) : "r"(a));
}
__device__ __forceinline__ void mma_f16(float* c, const uint32_t* a, const uint32_t* b) {
    asm volatile(
        "mma.sync.aligned.m16n8k16.row.col.f32.f16.f16.f32 "
        "{%0,%1,%2,%3}, {%4,%5,%6,%7}, {%8,%9}, {%0,%1,%2,%3};"
        : "+f"(c[0]), "+f"(c[1]), "+f"(c[2]), "+f"(c[3])
        : "r"(a[0]), "r"(a[1]), "r"(a[2]), "r"(a[3]), "r"(b[0]), "r"(b[1]));
}
__device__ __forceinline__ void mbar_init(uint32_t m, uint32_t cnt) {
    asm volatile("mbarrier.init.shared.b64 [%0], %1;" :: "r"(m), "r"(cnt) : "memory");
}
__device__ __forceinline__ void mbar_arrive(uint32_t m) {
    asm volatile("mbarrier.arrive.shared.b64 _, [%0];" :: "r"(m) : "memory");
}
__device__ __forceinline__ void mbar_wait(uint32_t m, uint32_t parity) {
    asm volatile(
        "{\n\t.reg .pred P;\n"
        "W%=:\n\t"
        "mbarrier.try_wait.parity.acquire.cta.shared::cta.b64 P, [%0], %1, 0x989680;\n\t"
        "@!P bra W%=;\n\t}"
        :: "r"(m), "r"(parity) : "memory");
}

__global__ __launch_bounds__(256, 2)
void bioconv_ws_kernel(const float* __restrict__ X,
                       const float* __restrict__ filt,
                       const float* __restrict__ bias,
                       float* __restrict__ out) {
    extern __shared__ __align__(16) char smem[];
    const uint32_t sb = smem_u32(smem);

    const int tid = threadIdx.x;
    const int l   = blockIdx.x;
    const int r   = l >> 4;
    const int cc  = l & 15;

    // mbarriers: full[s] at sb+s*16, empty[s] at sb+s*16+8
    if (tid == 0) {
        for (int s = 0; s < 4; ++s) {
            mbar_init(sb + s * 16, 128);      // full: 128 producer threads
            mbar_init(sb + s * 16 + 8, 128);  // empty: 128 consumer threads
        }
    }
    __syncthreads();

    if (tid >= 128) {
        // ================= PRODUCERS (warps 4-7) =================
        const int p  = tid - 128;
        const int ar = p >> 4, ac = p & 15;   // A f4: row v*8+ar, col ac (v 0..7)
        const int brr = p >> 5, bcc = p & 31; // B f4: row v*4+brr, col bcc (v 0..15)

        const float* gA0 = X + (size_t)ar * 262144 + r * 16384 + cc * 256 + ac * 4;
        const float* gB0 = filt + (size_t)l * 131072 + (size_t)brr * 128 + bcc * 4;
        const uint32_t a_sts = (uint32_t)(ar * AH + ac * 4) * 2;
        const uint32_t b_sts = (uint32_t)TA_B + (uint32_t)(brr * BH + bcc * 4) * 2;

        float4 fa[8], fbx[16];
        for (int t = 0; t < NCH; ++t) {
            const int s = t & 3;
            // LDG chunk t first (registers; independent of ring state)
            const float* ga = gA0 + (t >> 2) * 4096 + (t & 3) * 64;
#pragma unroll
            for (int v = 0; v < 8; ++v)
                fa[v] = *reinterpret_cast<const float4*>(ga + (size_t)v * 8 * 262144);
            const float* gb = gB0 + (size_t)t * 8192;
#pragma unroll
            for (int v = 0; v < 16; ++v)
                fbx[v] = *reinterpret_cast<const float4*>(gb + v * 512);

            if (t >= 4) mbar_wait(sb + s * 16 + 8, ((t - 4) >> 2) & 1);

            const uint32_t base = sb + OFF_STG + s * STG_B;
#pragma unroll
            for (int v = 0; v < 8; ++v)
                sts64(base + a_sts + v * 8 * (AH * 2),
                      pack_h2(fa[v].x, fa[v].y), pack_h2(fa[v].z, fa[v].w));
#pragma unroll
            for (int v = 0; v < 16; ++v)
                sts64(base + b_sts + v * 4 * (BH * 2),
                      pack_h2(fbx[v].x, fbx[v].y), pack_h2(fbx[v].z, fbx[v].w));
            mbar_arrive(sb + s * 16);  // full[s]
        }
        return;  // producers exit
    }

    // ================= CONSUMERS (warps 0-3) =================
    const int lane = tid & 31;
    const int cw   = tid >> 5;       // 0..3
    const int wm   = cw >> 1;        // M half (32 rows)
    const int wn   = cw & 1;         // N half (64 cols)
    const int g    = lane >> 2;
    const int t4   = lane & 3;

    const uint32_t a_rel = (uint32_t)(((wm * 32 + (lane & 15)) * AH + (lane >> 4) * 8) * 2);
    const uint32_t b_rel = (uint32_t)TA_B +
        (uint32_t)(((lane & 15) * BH + wn * 64 + ((lane >> 4) & 1) * 8) * 2);

    float acc[2][8][4];
#pragma unroll
    for (int i = 0; i < 2; ++i)
#pragma unroll
        for (int j = 0; j < 8; ++j)
#pragma unroll
            for (int k = 0; k < 4; ++k) acc[i][j][k] = 0.f;

    for (int t = 0; t < NCH; ++t) {
        const int s = t & 3;
        mbar_wait(sb + s * 16, (t >> 2) & 1);  // full[s]

        const uint32_t base = sb + OFF_STG + s * STG_B;
        const uint32_t aa = base + a_rel;
        const uint32_t bb = base + b_rel;

#pragma unroll
        for (int kh = 0; kh < 4; ++kh) {
            uint32_t A0[4], A1[4];
            ldmx4(A0, aa + kh * 32);
            ldmx4(A1, aa + 16 * (AH * 2) + kh * 32);
#pragma unroll
            for (int nq = 0; nq < 4; ++nq) {
                uint32_t Bq[4];
                ldmx4t(Bq, bb + kh * 16 * (BH * 2) + nq * 32);
                mma_f16(acc[0][nq * 2],     A0, &Bq[0]);
                mma_f16(acc[0][nq * 2 + 1], A0, &Bq[2]);
                mma_f16(acc[1][nq * 2],     A1, &Bq[0]);
                mma_f16(acc[1][nq * 2 + 1], A1, &Bq[2]);
            }
        }
        mbar_arrive(sb + s * 16 + 8);  // empty[s]
    }

    // ---- epilogue: bias + relu ----
#pragma unroll
    for (int nq = 0; nq < 8; ++nq) {
        const int n0 = wn * 64 + nq * 8 + t4 * 2;
        const float2 bv = *reinterpret_cast<const float2*>(bias + n0);
#pragma unroll
        for (int mt = 0; mt < 2; ++mt) {
            const int m = wm * 32 + mt * 16 + g;
            float2 o0, o1;
            o0.x = fmaxf(acc[mt][nq][0] + bv.x, 0.f);
            o0.y = fmaxf(acc[mt][nq][1] + bv.y, 0.f);
            o1.x = fmaxf(acc[mt][nq][2] + bv.x, 0.f);
            o1.y = fmaxf(acc[mt][nq][3] + bv.y, 0.f);
            *reinterpret_cast<float2*>(out + ((size_t)m * 256 + l) * 128 + n0) = o0;
            *reinterpret_cast<float2*>(out + ((size_t)(m + 8) * 256 + l) * 128 + n0) = o1;
        }
    }
}

}  // namespace

extern "C" void kernel_launch(void* const* d_in, const int* in_sizes, int n_in,
                              void* d_out, int out_size) {
    const float* X    = (const float*)d_in[0];
    const float* filt = (const float*)d_in[1];
    const float* bias = (const float*)d_in[2];
    float* out        = (float*)d_out;

    cudaFuncSetAttribute(bioconv_ws_kernel,
                         cudaFuncAttributeMaxDynamicSharedMemorySize, SMEM_BYTES);
    bioconv_ws_kernel<<<256, 256, SMEM_BYTES>>>(X, filt, bias, out);
}